// round 17
// baseline (speedup 1.0000x reference)
#include <cuda_runtime.h>
#include <cuda_fp16.h>
#include <cstdint>

// ---------------- problem constants ----------------
#define NB 4
#define NS 4096
#define NDIN 2048
#define NDOUT 2048
#define NR 16
#define NE 12
#define NM (NB * NS)  // 16384

// ---------------- GEMM tiling ----------------
#define BM 128
#define BN 128
#define CK 64                    // K per chunk (fp16): 128B rows
#define NCHUNK (NDIN / CK)       // 32
#define NCHTOT (NCHUNK + 1)      // +1 LoRA chunk (K=16 zero-padded to 64)
#define NSTAGE 3
#define NTILES 2048              // (NM/BM) * (NDOUT/BN)
#define GRID_P 296               // persistent CTAs: 2/SM x 148

#define PART_SZ 16384                        // 128 rows x 128B
#define OF_B PART_SZ
#define STAGE_SZ (2 * PART_SZ)               // 32768
#define OF_TILE 1024                         // mbarriers live below
#define SMEM_TOTAL (OF_TILE + NSTAGE * STAGE_SZ)   // 99328 (x2 CTAs < 228KB)

// ---------------- scratch (device globals: allocation-free rule) ----------------
__device__ __align__(16) __half g_x16[(size_t)NM * NDIN];
__device__ __align__(16) __half g_w16[(size_t)NDOUT * NDIN];
__device__ __align__(16) __half g_lx16[(size_t)NM * 64];          // cols 16-63 = 0
__device__ __align__(16) __half g_cb16[(size_t)NB * NDOUT * 64];  // cols 16-63 = 0

// ---------------- PTX helpers (plain sm_80+ instructions only) ----------------
__device__ __forceinline__ uint32_t smem_u32(const void* p) {
    uint32_t a;
    asm("{ .reg .u64 t; cvta.to.shared.u64 t, %1; cvt.u32.u64 %0, t; }" : "=r"(a) : "l"(p));
    return a;
}
__device__ __forceinline__ void cp16(uint32_t saddr, const void* gptr) {
    asm volatile("cp.async.cg.shared.global [%0], [%1], 16;"
                 :: "r"(saddr), "l"(__cvta_generic_to_global(gptr)) : "memory");
}
__device__ __forceinline__ void cp_commit() {
    asm volatile("cp.async.commit_group;" ::: "memory");
}
__device__ __forceinline__ void cp_wait1() {
    asm volatile("cp.async.wait_group 1;" ::: "memory");
}
// mbarrier ops (protocol validated end-to-end in R14-R16)
__device__ __forceinline__ void mbar_init(uint32_t a, uint32_t cnt) {
    asm volatile("mbarrier.init.shared.b64 [%0], %1;" :: "r"(a), "r"(cnt) : "memory");
}
__device__ __forceinline__ void mbar_arrive(uint32_t a) {
    asm volatile("mbarrier.arrive.shared.b64 _, [%0];" :: "r"(a) : "memory");
}
__device__ __forceinline__ void cp_arrive_noinc(uint32_t a) {
    asm volatile("cp.async.mbarrier.arrive.noinc.shared.b64 [%0];" :: "r"(a) : "memory");
}
__device__ __forceinline__ void mbar_wait(uint32_t a, uint32_t parity) {
    asm volatile(
        "{\n\t.reg .pred P;\n\t"
        "WL_%=:\n\t"
        "mbarrier.try_wait.parity.acquire.cta.shared::cta.b64 P, [%0], %1, 0x989680;\n\t"
        "@!P bra WL_%=;\n\t}"
        :: "r"(a), "r"(parity) : "memory");
}
#define LDSM4(r0, r1, r2, r3, addr)                                              \
    asm volatile("ldmatrix.sync.aligned.m8n8.x4.shared.b16 {%0,%1,%2,%3}, [%4];" \
                 : "=r"(r0), "=r"(r1), "=r"(r2), "=r"(r3) : "r"(addr))
#define MMAF16(c, a, b0, b1)                                                  \
    asm volatile("mma.sync.aligned.m16n8k16.row.col.f32.f16.f16.f32 "         \
                 "{%0,%1,%2,%3},{%4,%5,%6,%7},{%8,%9},{%0,%1,%2,%3};"         \
                 : "+f"((c)[0]), "+f"((c)[1]), "+f"((c)[2]), "+f"((c)[3])     \
                 : "r"((a)[0]), "r"((a)[1]), "r"((a)[2]), "r"((a)[3]),        \
                   "r"(b0), "r"(b1))

// 128B-row swizzle (validated since R7): 16B-chunk' = ch ^ (row&7)
__device__ __forceinline__ uint32_t swof(int row, int ch) {
    return (uint32_t)(row * 128 + ((ch ^ (row & 7)) << 4));
}

// ---------------- merged pre-kernel: cvt x + cvt W + gate-combine ----------------
union H8 { __half2 h[4]; uint4 u; };

__device__ __forceinline__ void cvt8h(const float* src, __half* dst, size_t i) {
    float4 v0 = *(const float4*)(src + i);
    float4 v1 = *(const float4*)(src + i + 4);
    H8 o;
    o.h[0] = __float22half2_rn(make_float2(v0.x, v0.y));
    o.h[1] = __float22half2_rn(make_float2(v0.z, v0.w));
    o.h[2] = __float22half2_rn(make_float2(v1.x, v1.y));
    o.h[3] = __float22half2_rn(make_float2(v1.z, v1.w));
    *(uint4*)(dst + i) = o.u;
}
// blocks [0,16384): cvt x; [16384,18432): cvt W_org; [18432,18944): combine
__global__ void k_cvt(const float* __restrict__ x,
                      const float* __restrict__ W_org,
                      const float* __restrict__ gate,
                      const float* __restrict__ W_up) {
    int bb = blockIdx.x;
    if (bb < 16384) {
        size_t i = ((size_t)bb * 256 + threadIdx.x) * 8;
        cvt8h(x, g_x16, i);
    } else if (bb < 18432) {
        size_t i = ((size_t)(bb - 16384) * 256 + threadIdx.x) * 8;
        cvt8h(W_org, g_w16, i);
    } else {
        int idx = (bb - 18432) * 256 + threadIdx.x;
        if (idx >= NB * NDOUT * NR) return;
        int b = idx / (NDOUT * NR);
        int orr = idx - b * (NDOUT * NR);
        int o = orr >> 4, r = orr & 15;
        float s = 0.f;
#pragma unroll
        for (int e = 0; e < NE; e++)
            s += __ldg(&gate[b * NE + e]) * __ldg(&W_up[(size_t)e * NDOUT * NR + orr]);
        size_t off = ((size_t)b * NDOUT + o) * 64;
        g_cb16[off + r] = __float2half_rn(s);
        if (r < 6) {  // zero cols 16..63
            uint4 z = make_uint4(0, 0, 0, 0);
            *(uint4*)&g_cb16[off + 16 + r * 8] = z;
        }
    }
}

// ---------------- k_lx: lx[m,0:16] = x @ W_down^T via fp16 mma ----------------
#define LXW 65536                        // 16 n-rows x 2048 k x 2B (fp16 W_down)
#define LX_ROWS 64
#define LX_STG (LX_ROWS * 128)           // 8192
#define LX_SMEM (LXW + 3 * LX_STG)       // 90112 -> 2 blocks/SM
#define LXCK 64
#define LXNCH (NDIN / LXCK)              // 32

__device__ __forceinline__ void lx_issue(uint32_t sb, int s, int c, int rowBase, int tid) {
    uint32_t xs = sb + LXW + s * LX_STG;
#pragma unroll
    for (int j = 0; j < 4; j++) {
        int g = tid + 128 * j;
        int row = g >> 3, ch = g & 7;
        cp16(xs + swof(row, ch),
             g_x16 + (size_t)(rowBase + row) * NDIN + c * LXCK + ch * 8);
    }
}

__global__ void __launch_bounds__(128, 2) k_lx(const float* __restrict__ Wd) {
    extern __shared__ char sm[];
    const uint32_t sb = smem_u32(sm);
    const int tid = threadIdx.x;
    const int w = tid >> 5, lane = tid & 31;
    const int rowBase = blockIdx.x * LX_ROWS;
    const int lr = lane & 15, lc = lane >> 4;

    for (int idx = tid; idx < 16 * 256; idx += 128) {
        int n = idx >> 8, ch = idx & 255;
        const float* s8 = Wd + (size_t)n * NDIN + ch * 8;
        float4 v0 = *(const float4*)s8;
        float4 v1 = *(const float4*)(s8 + 4);
        H8 o;
        o.h[0] = __float22half2_rn(make_float2(v0.x, v0.y));
        o.h[1] = __float22half2_rn(make_float2(v0.z, v0.w));
        o.h[2] = __float22half2_rn(make_float2(v1.x, v1.y));
        o.h[3] = __float22half2_rn(make_float2(v1.z, v1.w));
        *(uint4*)(sm + n * 4096 + ((ch ^ (n & 7)) << 4)) = o.u;
    }

    float acc[2][4];
#pragma unroll
    for (int j = 0; j < 2; j++)
#pragma unroll
        for (int q = 0; q < 4; q++) acc[j][q] = 0.f;

    lx_issue(sb, 0, 0, rowBase, tid); cp_commit();
    lx_issue(sb, 1, 1, rowBase, tid); cp_commit();

    for (int c = 0; c < LXNCH; c++) {
        cp_wait1();
        __syncthreads();
        if (c + 2 < LXNCH) lx_issue(sb, (c + 2) % 3, c + 2, rowBase, tid);
        cp_commit();
        const uint32_t xs = sb + LXW + (c % 3) * LX_STG;
#pragma unroll
        for (int ks = 0; ks < 4; ks++) {
            int K = c * 4 + ks;
            uint32_t chB = (uint32_t)(2 * K + lc);
            uint32_t r0, r1, r2, r3;
            LDSM4(r0, r1, r2, r3, sb + lr * 4096 + ((chB ^ (lr & 7)) << 4));
            uint32_t bf0[2] = {r0, r2}, bf1[2] = {r1, r3};
            int row = w * 16 + lr;
            uint32_t ch = (uint32_t)(ks * 2 + lc);
            uint32_t a[4];
            LDSM4(a[0], a[1], a[2], a[3],
                  xs + row * 128 + ((ch ^ (row & 7)) << 4));
            MMAF16(acc[0], a, bf0[0], bf0[1]);
            MMAF16(acc[1], a, bf1[0], bf1[1]);
        }
        __syncthreads();
    }

    {
        int row = rowBase + w * 16 + (lane >> 2);
#pragma unroll
        for (int nt = 0; nt < 2; nt++) {
            int col = nt * 8 + (lane & 3) * 2;
            *(__half2*)&g_lx16[(size_t)row * 64 + col] =
                __float22half2_rn(make_float2(acc[nt][0], acc[nt][1]));
            *(__half2*)&g_lx16[(size_t)(row + 8) * 64 + col] =
                __float22half2_rn(make_float2(acc[nt][2], acc[nt][3]));
        }
    }
    if (tid < LX_ROWS) {
        int m = rowBase + tid;
        uint4 z = make_uint4(0, 0, 0, 0);
#pragma unroll
        for (int zz = 0; zz < 6; zz++)
            *(uint4*)&g_lx16[(size_t)m * 64 + 16 + zz * 8] = z;
    }
}

// ---------------- main GEMM: persistent CTAs, continuous chunk stream ----------------
__global__ void __launch_bounds__(256, 2) k_gemm(float* __restrict__ out) {
    extern __shared__ char smem[];
    const uint32_t sb0 = smem_u32(smem);
    const int tid = threadIdx.x;
    const int wid = tid >> 5, lane = tid & 31;
    const int wm = wid >> 2, wn = wid & 3;      // warp tile 64x32
    const int lr = lane & 15, lc = lane >> 4;
    const uint32_t sw7 = (uint32_t)(lr & 7);

    const uint32_t mbF = sb0, mbE = sb0 + 24;
    if (tid == 0) {
#pragma unroll
        for (int s = 0; s < NSTAGE; s++) {
            mbar_init(mbF + s * 8, 256);
            mbar_init(mbE + s * 8, 8);
        }
    }
    __syncthreads();

    const uint32_t aBase0 = (uint32_t)((wm * 64 + lr) * 128);
    const uint32_t bBase0 = OF_B + (uint32_t)((wn * 32 + lr) * 128);
    uint32_t cx[4];
#pragma unroll
    for (int ks = 0; ks < 4; ks++)
        cx[ks] = ((uint32_t)(2 * ks + lc) ^ sw7) << 4;

    const int lrow = tid >> 3, lch = tid & 7;
    const uint32_t so0 = OF_TILE + swof(lrow, lch);

    // ---- producer tile state (tile p_t, next chunk p_kc) ----
    int p_t = blockIdx.x, p_kc = 0;
    const __half *paG, *pbG, *paL, *pbL;
    {
        int rb = (p_t >> 4) * BM, cb = (p_t & 15) * BN, bb = p_t >> 9;
        paG = g_x16 + (size_t)(rb + lrow) * NDIN + lch * 8;
        pbG = g_w16 + (size_t)(cb + lrow) * NDIN + lch * 8;
        paL = g_lx16 + (size_t)(rb + lrow) * 64 + lch * 8;
        pbL = g_cb16 + ((size_t)bb * NDOUT + cb + lrow) * 64 + lch * 8;
    }

    float acc[4][4][4];
#pragma unroll
    for (int i = 0; i < 4; i++)
#pragma unroll
        for (int j = 0; j < 4; j++)
#pragma unroll
            for (int q = 0; q < 4; q++) acc[i][j][q] = 0.f;

    // prologue: produce first 2 chunks of first tile (slots 0,1)
#pragma unroll
    for (int p = 0; p < 2; p++) {
        uint32_t s = sb0 + p * STAGE_SZ;
#pragma unroll
        for (int j = 0; j < 4; j++) {
            cp16(s + so0 + j * 4096, paG + p * CK + (size_t)j * 32 * NDIN);
            cp16(s + OF_B + so0 + j * 4096, pbG + p * CK + (size_t)j * 32 * NDIN);
        }
        cp_arrive_noinc(mbF + p * 8);
    }
    p_kc = 2;

    int c_t = blockIdx.x, c_kc = 0;
    int c_s = 0, c_p = 0;
    int p_s = 2, p_p = 1;

    while (c_t < NTILES) {
        // ---- consume one chunk ----
        mbar_wait(mbF + c_s * 8, (uint32_t)c_p);
        const uint32_t Sb = sb0 + OF_TILE + c_s * STAGE_SZ;

        uint32_t bfb[2][4][2];
        uint32_t a[3][4];
        {
            uint32_t r0, r1, r2, r3;
            LDSM4(r0, r1, r2, r3, Sb + bBase0 + cx[0]);
            bfb[0][0][0] = r0; bfb[0][0][1] = r2;
            bfb[0][1][0] = r1; bfb[0][1][1] = r3;
            LDSM4(r0, r1, r2, r3, Sb + bBase0 + 2048 + cx[0]);
            bfb[0][2][0] = r0; bfb[0][2][1] = r2;
            bfb[0][3][0] = r1; bfb[0][3][1] = r3;
            LDSM4(a[0][0], a[0][1], a[0][2], a[0][3], Sb + aBase0 + cx[0]);
            LDSM4(a[1][0], a[1][1], a[1][2], a[1][3], Sb + aBase0 + 2048 + cx[0]);
        }
#pragma unroll
        for (int ks = 0; ks < 4; ks++) {
            const int cur = ks & 1;
#pragma unroll
            for (int mt = 0; mt < 4; mt++) {
                const int step = ks * 4 + mt;
                if (mt == 0 && ks < 3) {
                    uint32_t r0, r1, r2, r3;
                    LDSM4(r0, r1, r2, r3, Sb + bBase0 + cx[ks + 1]);
                    bfb[cur ^ 1][0][0] = r0; bfb[cur ^ 1][0][1] = r2;
                    bfb[cur ^ 1][1][0] = r1; bfb[cur ^ 1][1][1] = r3;
                }
                if (mt == 1 && ks < 3) {
                    uint32_t r0, r1, r2, r3;
                    LDSM4(r0, r1, r2, r3, Sb + bBase0 + 2048 + cx[ks + 1]);
                    bfb[cur ^ 1][2][0] = r0; bfb[cur ^ 1][2][1] = r2;
                    bfb[cur ^ 1][3][0] = r1; bfb[cur ^ 1][3][1] = r3;
                }
                if (step + 2 < 16) {
                    const int ns = step + 2;
                    uint32_t* an = a[ns % 3];
                    LDSM4(an[0], an[1], an[2], an[3],
                          Sb + aBase0 + (ns & 3) * 2048 + cx[ns >> 2]);
                }
                if (ks == 3 && mt == 2 && lane == 0)
                    mbar_arrive(mbE + c_s * 8);   // last smem read was step 13
                const uint32_t* ac = a[step % 3];
#pragma unroll
                for (int nt = 0; nt < 4; nt++)
                    MMAF16(acc[mt][nt], ac, bfb[cur][nt][0], bfb[cur][nt][1]);
            }
        }
        if (++c_s == NSTAGE) { c_s = 0; c_p ^= 1; }
        const bool tile_done = (c_kc == NCHTOT - 1);
        c_kc = tile_done ? 0 : c_kc + 1;

        // ---- produce next chunk in stream (crosses tile boundaries) ----
        if (p_t < NTILES) {
            mbar_wait(mbE + p_s * 8, (uint32_t)p_p);
            uint32_t s = sb0 + p_s * STAGE_SZ;
            if (p_kc < NCHUNK) {
#pragma unroll
                for (int j = 0; j < 4; j++) {
                    cp16(s + so0 + j * 4096, paG + p_kc * CK + (size_t)j * 32 * NDIN);
                    cp16(s + OF_B + so0 + j * 4096, pbG + p_kc * CK + (size_t)j * 32 * NDIN);
                }
            } else {  // LoRA chunk
#pragma unroll
                for (int j = 0; j < 4; j++) {
                    cp16(s + so0 + j * 4096, paL + (size_t)j * 32 * 64);
                    cp16(s + OF_B + so0 + j * 4096, pbL + (size_t)j * 32 * 64);
                }
            }
            cp_arrive_noinc(mbF + p_s * 8);
            if (++p_s == NSTAGE) { p_s = 0; p_p ^= 1; }
            if (++p_kc == NCHTOT) {
                p_kc = 0;
                p_t += GRID_P;
                if (p_t < NTILES) {
                    int rb = (p_t >> 4) * BM, cb = (p_t & 15) * BN, bb = p_t >> 9;
                    paG = g_x16 + (size_t)(rb + lrow) * NDIN + lch * 8;
                    pbG = g_w16 + (size_t)(cb + lrow) * NDIN + lch * 8;
                    paL = g_lx16 + (size_t)(rb + lrow) * 64 + lch * 8;
                    pbL = g_cb16 + ((size_t)bb * NDOUT + cb + lrow) * 64 + lch * 8;
                }
            }
        }

        // ---- tile epilogue (next tile's data already in flight) ----
        if (tile_done) {
            int rowBase = (c_t >> 4) * BM, colBase = (c_t & 15) * BN;
#pragma unroll
            for (int mt = 0; mt < 4; mt++) {
#pragma unroll
                for (int nt = 0; nt < 4; nt++) {
                    int row = rowBase + wm * 64 + mt * 16 + (lane >> 2);
                    int col = colBase + wn * 32 + nt * 8 + (lane & 3) * 2;
                    *(float2*)&out[(size_t)row * NDOUT + col] =
                        make_float2(acc[mt][nt][0], acc[mt][nt][1]);
                    *(float2*)&out[(size_t)(row + 8) * NDOUT + col] =
                        make_float2(acc[mt][nt][2], acc[mt][nt][3]);
                    acc[mt][nt][0] = 0.f; acc[mt][nt][1] = 0.f;
                    acc[mt][nt][2] = 0.f; acc[mt][nt][3] = 0.f;
                }
            }
            c_t += GRID_P;
        }
    }
}

// ---------------- launch ----------------
extern "C" void kernel_launch(void* const* d_in, const int* in_sizes, int n_in,
                              void* d_out, int out_size) {
    const float* x      = (const float*)d_in[0];
    const float* gate   = (const float*)d_in[1];
    const float* W_org  = (const float*)d_in[2];
    const float* W_down = (const float*)d_in[3];
    const float* W_up   = (const float*)d_in[4];
    float* out = (float*)d_out;

    cudaFuncSetAttribute(k_gemm, cudaFuncAttributeMaxDynamicSharedMemorySize, SMEM_TOTAL);
    cudaFuncSetAttribute(k_lx, cudaFuncAttributeMaxDynamicSharedMemorySize, LX_SMEM);

    k_cvt<<<16384 + 2048 + 512, 256>>>(x, W_org, gate, W_up);
    k_lx<<<NM / LX_ROWS, 128, LX_SMEM>>>(W_down);

    k_gemm<<<GRID_P, 256, SMEM_TOTAL>>>(out);
}